// round 2
// baseline (speedup 1.0000x reference)
#include <cuda_runtime.h>

#define BB   16
#define CC   512
#define NTOK 1024
#define HEADS 8
#define CHD  64
#define NG   32
#define CPG  16
#define EPSV 1e-5f

// Scratch (static device arrays: allocation-free per harness rules)
__device__ float g_xn [BB * CC * NTOK];        // 32 MB  group-normed x
__device__ float g_qkv[BB * 3 * CC * NTOK];    // 96 MB  qkv
__device__ float g_att[BB * CC * NTOK];        // 32 MB  attention output

// ---------------------------------------------------------------------------
// Kernel 1: fused GroupNorm (stats + normalize). 1 block per (batch, group).
// ---------------------------------------------------------------------------
__global__ void gn_kernel(const float* __restrict__ x, const float* __restrict__ w,
                          const float* __restrict__ bias, float* __restrict__ xn) {
    int bg = blockIdx.x;
    int b = bg / NG, g = bg % NG;
    const float4* xp = (const float4*)(x + ((size_t)b * CC + g * CPG) * NTOK);
    float4* xo = (float4*)(xn + ((size_t)b * CC + g * CPG) * NTOK);

    float s = 0.f, ss = 0.f;
    for (int i = threadIdx.x; i < CPG * NTOK / 4; i += 256) {
        float4 v = xp[i];
        s  += v.x + v.y + v.z + v.w;
        ss += v.x * v.x + v.y * v.y + v.z * v.z + v.w * v.w;
    }
    #pragma unroll
    for (int off = 16; off; off >>= 1) {
        s  += __shfl_xor_sync(0xffffffffu, s, off);
        ss += __shfl_xor_sync(0xffffffffu, ss, off);
    }
    __shared__ float rs[8], rss[8];
    __shared__ float bmean, binv;
    int wid = threadIdx.x >> 5, lid = threadIdx.x & 31;
    if (lid == 0) { rs[wid] = s; rss[wid] = ss; }
    __syncthreads();
    if (threadIdx.x == 0) {
        float S = 0.f, SS = 0.f;
        #pragma unroll
        for (int i = 0; i < 8; i++) { S += rs[i]; SS += rss[i]; }
        float mean = S * (1.0f / (CPG * NTOK));
        float var  = SS * (1.0f / (CPG * NTOK)) - mean * mean;
        bmean = mean;
        binv  = rsqrtf(var + EPSV);
    }
    __syncthreads();
    float mean = bmean, inv = binv;
    for (int i = threadIdx.x; i < CPG * NTOK / 4; i += 256) {
        int c = g * CPG + (i * 4) / NTOK;
        float wc = w[c] * inv;
        float bc = bias[c] - mean * wc;
        float4 v = xp[i];
        v.x = v.x * wc + bc; v.y = v.y * wc + bc;
        v.z = v.z * wc + bc; v.w = v.w * wc + bc;
        xo[i] = v;
    }
}

// ---------------------------------------------------------------------------
// Kernel 2/4: tiled SGEMM  Y[b,m,n] = sum_c W[m,c]*X[b,c,n] + bias[m] (+resid)
// BM=BN=128, BK=16, 256 threads, 8x8 microtile.
// ---------------------------------------------------------------------------
template <bool RESID>
__global__ void gemm_kernel(const float* __restrict__ Wm, const float* __restrict__ X,
                            const float* __restrict__ bias, const float* __restrict__ Rz,
                            float* __restrict__ Y, int M) {
    const int Kd = CC;  // 512 in both uses
    __shared__ float As[16][128];
    __shared__ float Bs[16][128];

    int tid = threadIdx.x;
    int tx = tid & 15, ty = tid >> 4;
    int bx = blockIdx.x, by = blockIdx.y, b = blockIdx.z;
    const float* Xb = X + (size_t)b * Kd * NTOK;

    int a_row = tid >> 2;            // 0..63
    int a_col = (tid & 3) << 2;      // 0,4,8,12
    int b_row = tid >> 5;            // 0..7
    int b_col = (tid & 31) << 2;     // 0..124

    float acc[8][8];
    #pragma unroll
    for (int i = 0; i < 8; i++)
        #pragma unroll
        for (int j = 0; j < 8; j++) acc[i][j] = 0.f;

    for (int k0 = 0; k0 < Kd; k0 += 16) {
        #pragma unroll
        for (int rr = 0; rr < 2; rr++) {
            int m = a_row + rr * 64;
            float4 v = *(const float4*)&Wm[(size_t)(by * 128 + m) * Kd + k0 + a_col];
            As[a_col + 0][m] = v.x; As[a_col + 1][m] = v.y;
            As[a_col + 2][m] = v.z; As[a_col + 3][m] = v.w;
            int k = b_row + rr * 8;
            *(float4*)&Bs[k][b_col] =
                *(const float4*)&Xb[(size_t)(k0 + k) * NTOK + bx * 128 + b_col];
        }
        __syncthreads();
        #pragma unroll
        for (int kk = 0; kk < 16; kk++) {
            float4 a0 = *(const float4*)&As[kk][ty * 8];
            float4 a1 = *(const float4*)&As[kk][ty * 8 + 4];
            float4 b0 = *(const float4*)&Bs[kk][tx * 8];
            float4 b1 = *(const float4*)&Bs[kk][tx * 8 + 4];
            float a[8] = {a0.x, a0.y, a0.z, a0.w, a1.x, a1.y, a1.z, a1.w};
            float bv[8] = {b0.x, b0.y, b0.z, b0.w, b1.x, b1.y, b1.z, b1.w};
            #pragma unroll
            for (int i = 0; i < 8; i++)
                #pragma unroll
                for (int j = 0; j < 8; j++) acc[i][j] += a[i] * bv[j];
        }
        __syncthreads();
    }

    #pragma unroll
    for (int i = 0; i < 8; i++) {
        int m = by * 128 + ty * 8 + i;
        float bv = bias[m];
        size_t off = ((size_t)b * M + m) * NTOK + bx * 128 + tx * 8;
        float4 o0 = make_float4(acc[i][0] + bv, acc[i][1] + bv, acc[i][2] + bv, acc[i][3] + bv);
        float4 o1 = make_float4(acc[i][4] + bv, acc[i][5] + bv, acc[i][6] + bv, acc[i][7] + bv);
        if (RESID) {
            float4 r0 = *(const float4*)&Rz[off];
            float4 r1 = *(const float4*)&Rz[off + 4];
            o0.x += r0.x; o0.y += r0.y; o0.z += r0.z; o0.w += r0.w;
            o1.x += r1.x; o1.y += r1.y; o1.z += r1.z; o1.w += r1.w;
        }
        *(float4*)&Y[off]     = o0;
        *(float4*)&Y[off + 4] = o1;
    }
}

// ---------------------------------------------------------------------------
// Kernel 3: fp32 flash attention. Block = (128 queries) of one (b, head).
// BK=64 key tile, 16 tiles. q/k/v layout: [b][3C][n] with d-major rows.
// ---------------------------------------------------------------------------
#define FLASH_SMEM (98560)
__global__ void flash_kernel(const float* __restrict__ qkv, float* __restrict__ att) {
    extern __shared__ float sm[];
    float* Qs = sm;                 // [64][128]
    float* Ks = sm + 8192;          // [64][64]
    float* Vt = sm + 12288;         // [64][65] (j-major, padded)
    float* Ps = sm + 16448;         // [128][64]

    int tid = threadIdx.x;
    int tx = tid & 15, ty = tid >> 4;
    int qb = blockIdx.x, hh = blockIdx.y, b = blockIdx.z;

    const float* qp = qkv + ((size_t)b * 3 * CC + hh * CHD) * NTOK;
    const float* kp = qp + (size_t)CC * NTOK;
    const float* vp = qp + (size_t)2 * CC * NTOK;
    int q0 = qb * 128;

    #pragma unroll
    for (int rep = 0; rep < 8; rep++) {
        int idx = rep * 256 + tid;
        int d = idx >> 5, i4 = (idx & 31) << 2;
        *(float4*)&Qs[d * 128 + i4] = *(const float4*)&qp[d * NTOK + q0 + i4];
    }

    float m_i[8], l_i[8], O[8][4];
    #pragma unroll
    for (int i = 0; i < 8; i++) {
        m_i[i] = -1e30f; l_i[i] = 0.f;
        #pragma unroll
        for (int j = 0; j < 4; j++) O[i][j] = 0.f;
    }

    for (int kt = 0; kt < 16; kt++) {
        int k0 = kt * 64;
        #pragma unroll
        for (int rep = 0; rep < 4; rep++) {
            int idx = rep * 256 + tid;
            int d = idx >> 4, j4 = (idx & 15) << 2;
            *(float4*)&Ks[d * 64 + j4] = *(const float4*)&kp[d * NTOK + k0 + j4];
            float4 vv = *(const float4*)&vp[d * NTOK + k0 + j4];
            Vt[(j4 + 0) * 65 + d] = vv.x;
            Vt[(j4 + 1) * 65 + d] = vv.y;
            Vt[(j4 + 2) * 65 + d] = vv.z;
            Vt[(j4 + 3) * 65 + d] = vv.w;
        }
        __syncthreads();

        float s[8][4];
        #pragma unroll
        for (int i = 0; i < 8; i++)
            #pragma unroll
            for (int j = 0; j < 4; j++) s[i][j] = 0.f;

        #pragma unroll 4
        for (int d = 0; d < 64; d++) {
            float4 a0 = *(const float4*)&Qs[d * 128 + ty * 8];
            float4 a1 = *(const float4*)&Qs[d * 128 + ty * 8 + 4];
            float4 kb = *(const float4*)&Ks[d * 64 + tx * 4];
            float a[8] = {a0.x, a0.y, a0.z, a0.w, a1.x, a1.y, a1.z, a1.w};
            float bv[4] = {kb.x, kb.y, kb.z, kb.w};
            #pragma unroll
            for (int i = 0; i < 8; i++)
                #pragma unroll
                for (int j = 0; j < 4; j++) s[i][j] += a[i] * bv[j];
        }

        #pragma unroll
        for (int i = 0; i < 8; i++) {
            float mx = -1e30f;
            #pragma unroll
            for (int j = 0; j < 4; j++) { s[i][j] *= 0.125f; mx = fmaxf(mx, s[i][j]); }
            #pragma unroll
            for (int off = 1; off < 16; off <<= 1)
                mx = fmaxf(mx, __shfl_xor_sync(0xffffffffu, mx, off));
            float m_new = fmaxf(m_i[i], mx);
            float corr = __expf(m_i[i] - m_new);
            float rsum = 0.f;
            #pragma unroll
            for (int j = 0; j < 4; j++) {
                float p = __expf(s[i][j] - m_new);
                s[i][j] = p; rsum += p;
            }
            #pragma unroll
            for (int off = 1; off < 16; off <<= 1)
                rsum += __shfl_xor_sync(0xffffffffu, rsum, off);
            l_i[i] = l_i[i] * corr + rsum;
            m_i[i] = m_new;
            #pragma unroll
            for (int j = 0; j < 4; j++) O[i][j] *= corr;
            *(float4*)&Ps[(ty * 8 + i) * 64 + tx * 4] =
                make_float4(s[i][0], s[i][1], s[i][2], s[i][3]);
        }
        __syncthreads();

        // PV: scalar LDS from Vt (rows padded to 65 floats -> float4 would be
        // misaligned; scalar reads are 16B-alignment-free and ~2-way conflict).
        #pragma unroll 4
        for (int j = 0; j < 64; j++) {
            int vb = j * 65 + tx * 4;
            float v0 = Vt[vb + 0];
            float v1 = Vt[vb + 1];
            float v2 = Vt[vb + 2];
            float v3 = Vt[vb + 3];
            #pragma unroll
            for (int i = 0; i < 8; i++) {
                float p = Ps[(ty * 8 + i) * 64 + j];
                O[i][0] += p * v0; O[i][1] += p * v1;
                O[i][2] += p * v2; O[i][3] += p * v3;
            }
        }
        __syncthreads();
    }

    float* ap = att + ((size_t)b * CC + hh * CHD) * NTOK;
    #pragma unroll
    for (int i = 0; i < 8; i++) {
        float invl = 1.f / l_i[i];
        #pragma unroll
        for (int dd = 0; dd < 4; dd++)
            ap[(tx * 4 + dd) * NTOK + q0 + ty * 8 + i] = O[i][dd] * invl;
    }
}

// ---------------------------------------------------------------------------
extern "C" void kernel_launch(void* const* d_in, const int* in_sizes, int n_in,
                              void* d_out, int out_size) {
    (void)in_sizes; (void)n_in; (void)out_size;
    const float* x  = (const float*)d_in[0];
    const float* nw = (const float*)d_in[1];
    const float* nb = (const float*)d_in[2];
    const float* qw = (const float*)d_in[3];
    const float* qb = (const float*)d_in[4];
    const float* pw = (const float*)d_in[5];
    const float* pb = (const float*)d_in[6];
    float* out = (float*)d_out;

    float *xn, *qkv, *att;
    cudaGetSymbolAddress((void**)&xn,  g_xn);
    cudaGetSymbolAddress((void**)&qkv, g_qkv);
    cudaGetSymbolAddress((void**)&att, g_att);
    cudaFuncSetAttribute(flash_kernel, cudaFuncAttributeMaxDynamicSharedMemorySize, FLASH_SMEM);

    gn_kernel<<<BB * NG, 256>>>(x, nw, nb, xn);
    gemm_kernel<false><<<dim3(NTOK / 128, 1536 / 128, BB), 256>>>(qw, xn, qb, nullptr, qkv, 1536);
    flash_kernel<<<dim3(NTOK / 128, HEADS, BB), 256, FLASH_SMEM>>>(qkv, att);
    gemm_kernel<true><<<dim3(NTOK / 128, 512 / 128, BB), 256>>>(pw, att, pb, x, out, 512);
}

// round 4
// speedup vs baseline: 3.1137x; 3.1137x over previous
#include <cuda_runtime.h>
#include <cuda_fp16.h>
#include <cstdint>

#define BB   16
#define CC   512
#define NTOK 1024
#define HEADS 8
#define CHD  64
#define NG   32
#define CPG  16
#define EPSV 1e-5f

// Scratch (static device arrays: allocation-free per harness rules)
__device__ float g_xn [BB * CC * NTOK];        // 32 MB  group-normed x
__device__ float g_qkv[BB * 3 * CC * NTOK];    // 96 MB  qkv
__device__ float g_att[BB * CC * NTOK];        // 32 MB  attention output

// ===========================================================================
// Helpers: swizzle, ldmatrix, mma.sync (all plain-sm_103 legal, sm_80 era)
// ===========================================================================
#define SWZ(x) ((uint32_t)(x) ^ ((((uint32_t)(x)) >> 3) & 0x70u))

static __device__ __forceinline__ uint32_t smem_u32(const void* p) {
    uint32_t a;
    asm("{ .reg .u64 t; cvta.to.shared.u64 t, %1; cvt.u32.u64 %0, t; }" : "=r"(a) : "l"(p));
    return a;
}

#define LDSM_X4(r0, r1, r2, r3, addr) \
    asm volatile("ldmatrix.sync.aligned.m8n8.x4.shared.b16 {%0,%1,%2,%3}, [%4];" \
        : "=r"(r0), "=r"(r1), "=r"(r2), "=r"(r3) : "r"(addr))

#define MMA4(c, a0, a1, a2, a3, b0, b1) \
    asm volatile("mma.sync.aligned.m16n8k16.row.col.f32.f16.f16.f32 " \
        "{%0,%1,%2,%3}, {%4,%5,%6,%7}, {%8,%9}, {%0,%1,%2,%3};" \
        : "+f"((c)[0]), "+f"((c)[1]), "+f"((c)[2]), "+f"((c)[3]) \
        : "r"(a0), "r"(a1), "r"(a2), "r"(a3), "r"(b0), "r"(b1))

static __device__ __forceinline__ uint32_t h2u(__half2 h) {
    return *reinterpret_cast<uint32_t*>(&h);
}
static __device__ __forceinline__ uint32_t pack2(float a, float b) {
    __half2 h = __floats2half2_rn(a, b);
    return h2u(h);
}
// fp32 -> fp16 hi + fp16 lo (2-term split), packed pairs
static __device__ __forceinline__ void split2(float a, float b, uint32_t& hp, uint32_t& lp) {
    __half ha = __float2half_rn(a), hb = __float2half_rn(b);
    float la = a - __half2float(ha), lb = b - __half2float(hb);
    __half2 h = __halves2half2(ha, hb);
    hp = h2u(h);
    lp = pack2(la, lb);
}

// ---------------------------------------------------------------------------
// Kernel 1: fused GroupNorm (stats + normalize). 1 block per (batch, group).
// ---------------------------------------------------------------------------
__global__ void gn_kernel(const float* __restrict__ x, const float* __restrict__ w,
                          const float* __restrict__ bias, float* __restrict__ xn) {
    int bg = blockIdx.x;
    int b = bg / NG, g = bg % NG;
    const float4* xp = (const float4*)(x + ((size_t)b * CC + g * CPG) * NTOK);
    float4* xo = (float4*)(xn + ((size_t)b * CC + g * CPG) * NTOK);

    float s = 0.f, ss = 0.f;
    for (int i = threadIdx.x; i < CPG * NTOK / 4; i += 256) {
        float4 v = xp[i];
        s  += v.x + v.y + v.z + v.w;
        ss += v.x * v.x + v.y * v.y + v.z * v.z + v.w * v.w;
    }
    #pragma unroll
    for (int off = 16; off; off >>= 1) {
        s  += __shfl_xor_sync(0xffffffffu, s, off);
        ss += __shfl_xor_sync(0xffffffffu, ss, off);
    }
    __shared__ float rs[8], rss[8];
    __shared__ float bmean, binv;
    int wid = threadIdx.x >> 5, lid = threadIdx.x & 31;
    if (lid == 0) { rs[wid] = s; rss[wid] = ss; }
    __syncthreads();
    if (threadIdx.x == 0) {
        float S = 0.f, SS = 0.f;
        #pragma unroll
        for (int i = 0; i < 8; i++) { S += rs[i]; SS += rss[i]; }
        float mean = S * (1.0f / (CPG * NTOK));
        float var  = SS * (1.0f / (CPG * NTOK)) - mean * mean;
        bmean = mean;
        binv  = rsqrtf(var + EPSV);
    }
    __syncthreads();
    float mean = bmean, inv = binv;
    for (int i = threadIdx.x; i < CPG * NTOK / 4; i += 256) {
        int c = g * CPG + (i * 4) / NTOK;
        float wc = w[c] * inv;
        float bc = bias[c] - mean * wc;
        float4 v = xp[i];
        v.x = v.x * wc + bc; v.y = v.y * wc + bc;
        v.z = v.z * wc + bc; v.w = v.w * wc + bc;
        xo[i] = v;
    }
}

// ---------------------------------------------------------------------------
// Kernel 2/4: fp16 HMMA GEMM with 2-term split on B (activations).
// Y[b,m,n] = sum_c W[m,c]*X[b,c,n] + bias[m] (+resid)
// CTA: 128m x 128n x K512 (8 K-blocks of 64), 8 warps = 2m x 4n, warp 64x32.
// smem: A[m][k] fp16 hi (16KB), B[n][k] fp16 hi (16KB) + lo (16KB). SW128.
// ---------------------------------------------------------------------------
#define GEMM_SMEM 49152

template <bool RESID>
__global__ void __launch_bounds__(256, 2)
gemm_hmma(const float* __restrict__ W, const float* __restrict__ X,
          const float* __restrict__ bias, const float* __restrict__ Rz,
          float* __restrict__ Y, int Mtot) {
    extern __shared__ char smem[];
    const uint32_t sb = smem_u32(smem);
    const uint32_t sA = sb, sBh = sb + 16384, sBl = sb + 32768;
    const int tid = threadIdx.x, lane = tid & 31, w = tid >> 5;
    const int wm = w & 1, wn = w >> 1;
    const int g = lane >> 3, r = lane & 7;
    const int n0 = blockIdx.x * 128, m0 = blockIdx.y * 128, b = blockIdx.z;
    const float* Xb = X + (size_t)b * CC * NTOK;

    float acc[4][4][4];
    #pragma unroll
    for (int i = 0; i < 4; i++)
        #pragma unroll
        for (int j = 0; j < 4; j++)
            #pragma unroll
            for (int e = 0; e < 4; e++) acc[i][j][e] = 0.f;

    for (int kb = 0; kb < 8; kb++) {
        const int k0 = kb * 64;
        if (kb) __syncthreads();

        // A fill: W[m0..+127][k0..+63] -> fp16 hi, [m][k] SW128
        #pragma unroll
        for (int it = 0; it < 8; it++) {
            int idx = it * 256 + tid;
            int row = idx >> 4, f4 = idx & 15;
            float4 v = *(const float4*)&W[(size_t)(m0 + row) * CC + k0 + f4 * 4];
            uint2 hp = make_uint2(pack2(v.x, v.y), pack2(v.z, v.w));
            *(uint2*)(smem + SWZ(row * 128 + f4 * 8)) = hp;
        }
        // B fill: X[k][n] -> transpose to [n][k], fp16 hi + lo
        #pragma unroll
        for (int it = 0; it < 2; it++) {
            int k = ((tid & 7) + it * 8) * 4;
            int n = (tid >> 3) * 4;
            float4 r0 = *(const float4*)&Xb[(size_t)(k0 + k + 0) * NTOK + n0 + n];
            float4 r1 = *(const float4*)&Xb[(size_t)(k0 + k + 1) * NTOK + n0 + n];
            float4 r2 = *(const float4*)&Xb[(size_t)(k0 + k + 2) * NTOK + n0 + n];
            float4 r3 = *(const float4*)&Xb[(size_t)(k0 + k + 3) * NTOK + n0 + n];
            float vr[4][4] = {{r0.x, r0.y, r0.z, r0.w}, {r1.x, r1.y, r1.z, r1.w},
                              {r2.x, r2.y, r2.z, r2.w}, {r3.x, r3.y, r3.z, r3.w}};
            #pragma unroll
            for (int j = 0; j < 4; j++) {
                uint32_t h0, l0, h1, l1;
                split2(vr[0][j], vr[1][j], h0, l0);
                split2(vr[2][j], vr[3][j], h1, l1);
                uint32_t so = SWZ((n + j) * 128 + k * 2);
                *(uint2*)(smem + 16384 + so) = make_uint2(h0, h1);
                *(uint2*)(smem + 32768 + so) = make_uint2(l0, l1);
            }
        }
        __syncthreads();

        #pragma unroll
        for (int ks = 0; ks < 4; ks++) {
            uint32_t a[4][4];
            #pragma unroll
            for (int mt = 0; mt < 4; mt++) {
                uint32_t ad = sA + SWZ((wm * 64 + mt * 16 + (g & 1) * 8 + r) * 128
                                       + ks * 32 + (g >> 1) * 16);
                LDSM_X4(a[mt][0], a[mt][1], a[mt][2], a[mt][3], ad);
            }
            uint32_t bb[4][2];
            #pragma unroll
            for (int p = 0; p < 2; p++) {
                uint32_t bd = sBh + SWZ((wn * 32 + p * 16 + (g >> 1) * 8 + r) * 128
                                        + ks * 32 + (g & 1) * 16);
                LDSM_X4(bb[2*p][0], bb[2*p][1], bb[2*p+1][0], bb[2*p+1][1], bd);
            }
            #pragma unroll
            for (int mt = 0; mt < 4; mt++)
                #pragma unroll
                for (int nt = 0; nt < 4; nt++)
                    MMA4(acc[mt][nt], a[mt][0], a[mt][1], a[mt][2], a[mt][3],
                         bb[nt][0], bb[nt][1]);
            #pragma unroll
            for (int p = 0; p < 2; p++) {
                uint32_t bd = sBl + SWZ((wn * 32 + p * 16 + (g >> 1) * 8 + r) * 128
                                        + ks * 32 + (g & 1) * 16);
                LDSM_X4(bb[2*p][0], bb[2*p][1], bb[2*p+1][0], bb[2*p+1][1], bd);
            }
            #pragma unroll
            for (int mt = 0; mt < 4; mt++)
                #pragma unroll
                for (int nt = 0; nt < 4; nt++)
                    MMA4(acc[mt][nt], a[mt][0], a[mt][1], a[mt][2], a[mt][3],
                         bb[nt][0], bb[nt][1]);
        }
    }

    // Epilogue: C frag (row=lane>>2, col=2*(lane&3)), rows +8 for c2,c3
    const int qrow = lane >> 2, qcol = (lane & 3) * 2;
    #pragma unroll
    for (int mt = 0; mt < 4; mt++) {
        int mr0 = m0 + wm * 64 + mt * 16 + qrow;
        float bv0 = bias[mr0], bv1 = bias[mr0 + 8];
        #pragma unroll
        for (int nt = 0; nt < 4; nt++) {
            int col = n0 + wn * 32 + nt * 8 + qcol;
            size_t o0 = ((size_t)b * Mtot + mr0) * NTOK + col;
            size_t o1 = o0 + (size_t)8 * NTOK;
            float2 v0 = make_float2(acc[mt][nt][0] + bv0, acc[mt][nt][1] + bv0);
            float2 v1 = make_float2(acc[mt][nt][2] + bv1, acc[mt][nt][3] + bv1);
            if (RESID) {
                float2 z0 = *(const float2*)&Rz[o0];
                float2 z1 = *(const float2*)&Rz[o1];
                v0.x += z0.x; v0.y += z0.y;
                v1.x += z1.x; v1.y += z1.y;
            }
            *(float2*)&Y[o0] = v0;
            *(float2*)&Y[o1] = v1;
        }
    }
}

// ---------------------------------------------------------------------------
// Kernel 3: fp16 HMMA flash attention. CTA = 128 queries of one (b, head).
// 8 warps, warp owns 16 query rows (softmax fully warp-local).
// smem: Q[i][d] 16KB, K[j][d] 16KB (SW128), V[d][j] padded stride 272B.
// ---------------------------------------------------------------------------
#define FLASH_SMEM (16384 + 16384 + 64 * 272)

__global__ void __launch_bounds__(256, 2)
flash_hmma(const float* __restrict__ qkv, float* __restrict__ att) {
    extern __shared__ char fsm[];
    const uint32_t sb = smem_u32(fsm);
    const uint32_t sQ = sb, sK = sb + 16384, sV = sb + 32768;
    const int tid = threadIdx.x, lane = tid & 31, w = tid >> 5;
    const int g = lane >> 3, r = lane & 7;
    const int qrow = lane >> 2, qcol = (lane & 3) * 2;
    const int qb = blockIdx.x, hh = blockIdx.y, b = blockIdx.z;

    const float* qp = qkv + ((size_t)b * 3 * CC + hh * CHD) * NTOK;
    const float* kp = qp + (size_t)CC * NTOK;
    const float* vp = qp + (size_t)2 * CC * NTOK;
    const int q0 = qb * 128;

    // Q fill: transpose [d][i] -> [i][d] fp16, SW128
    #pragma unroll
    for (int it = 0; it < 2; it++) {
        int d = ((tid & 7) + it * 8) * 4;
        int i = (tid >> 3) * 4;
        float4 r0 = *(const float4*)&qp[(size_t)(d + 0) * NTOK + q0 + i];
        float4 r1 = *(const float4*)&qp[(size_t)(d + 1) * NTOK + q0 + i];
        float4 r2 = *(const float4*)&qp[(size_t)(d + 2) * NTOK + q0 + i];
        float4 r3 = *(const float4*)&qp[(size_t)(d + 3) * NTOK + q0 + i];
        float vr[4][4] = {{r0.x, r0.y, r0.z, r0.w}, {r1.x, r1.y, r1.z, r1.w},
                          {r2.x, r2.y, r2.z, r2.w}, {r3.x, r3.y, r3.z, r3.w}};
        #pragma unroll
        for (int j = 0; j < 4; j++) {
            uint32_t so = SWZ((i + j) * 128 + d * 2);
            *(uint2*)(fsm + so) = make_uint2(pack2(vr[0][j], vr[1][j]),
                                             pack2(vr[2][j], vr[3][j]));
        }
    }

    float m0r = -1e30f, m1r = -1e30f, l0r = 0.f, l1r = 0.f;
    float O[8][4];
    #pragma unroll
    for (int i = 0; i < 8; i++)
        #pragma unroll
        for (int e = 0; e < 4; e++) O[i][e] = 0.f;

    for (int kt = 0; kt < 8; kt++) {
        const int k0 = kt * 128;
        __syncthreads();   // prior compute done before refilling K/V (also covers Q fill)

        // K fill: transpose [d][j] -> [j][d] fp16, SW128
        #pragma unroll
        for (int it = 0; it < 2; it++) {
            int d = ((tid & 7) + it * 8) * 4;
            int j = (tid >> 3) * 4;
            float4 r0 = *(const float4*)&kp[(size_t)(d + 0) * NTOK + k0 + j];
            float4 r1 = *(const float4*)&kp[(size_t)(d + 1) * NTOK + k0 + j];
            float4 r2 = *(const float4*)&kp[(size_t)(d + 2) * NTOK + k0 + j];
            float4 r3 = *(const float4*)&kp[(size_t)(d + 3) * NTOK + k0 + j];
            float vr[4][4] = {{r0.x, r0.y, r0.z, r0.w}, {r1.x, r1.y, r1.z, r1.w},
                              {r2.x, r2.y, r2.z, r2.w}, {r3.x, r3.y, r3.z, r3.w}};
            #pragma unroll
            for (int jj = 0; jj < 4; jj++) {
                uint32_t so = SWZ((j + jj) * 128 + d * 2);
                *(uint2*)(fsm + 16384 + so) = make_uint2(pack2(vr[0][jj], vr[1][jj]),
                                                         pack2(vr[2][jj], vr[3][jj]));
            }
        }
        // V fill: direct [d][j] fp16, padded row stride 272B (conflict-free LDSM)
        #pragma unroll
        for (int it = 0; it < 8; it++) {
            int idx = it * 256 + tid;
            int d = idx >> 5, f4 = idx & 31;
            float4 v = *(const float4*)&vp[(size_t)d * NTOK + k0 + f4 * 4];
            *(uint2*)(fsm + 32768 + d * 272 + f4 * 8) =
                make_uint2(pack2(v.x, v.y), pack2(v.z, v.w));
        }
        __syncthreads();

        // S = Q K^T (warp rows w*16..+15, all 128 cols)
        float S[16][4];
        #pragma unroll
        for (int nt = 0; nt < 16; nt++)
            #pragma unroll
            for (int e = 0; e < 4; e++) S[nt][e] = 0.f;

        #pragma unroll
        for (int ks = 0; ks < 4; ks++) {
            uint32_t a0, a1, a2, a3;
            uint32_t ad = sQ + SWZ((w * 16 + (g & 1) * 8 + r) * 128
                                   + ks * 32 + (g >> 1) * 16);
            LDSM_X4(a0, a1, a2, a3, ad);
            #pragma unroll
            for (int p = 0; p < 8; p++) {
                uint32_t b0, b1, b2, b3;
                uint32_t bd = sK + SWZ((p * 16 + (g >> 1) * 8 + r) * 128
                                       + ks * 32 + (g & 1) * 16);
                LDSM_X4(b0, b1, b2, b3, bd);
                MMA4(S[2*p],   a0, a1, a2, a3, b0, b1);
                MMA4(S[2*p+1], a0, a1, a2, a3, b2, b3);
            }
        }

        // online softmax (rows qrow / qrow+8, quad-reduced over lanes)
        float mx0 = -1e30f, mx1 = -1e30f;
        #pragma unroll
        for (int nt = 0; nt < 16; nt++) {
            S[nt][0] *= 0.125f; S[nt][1] *= 0.125f;
            S[nt][2] *= 0.125f; S[nt][3] *= 0.125f;
            mx0 = fmaxf(mx0, fmaxf(S[nt][0], S[nt][1]));
            mx1 = fmaxf(mx1, fmaxf(S[nt][2], S[nt][3]));
        }
        mx0 = fmaxf(mx0, __shfl_xor_sync(0xffffffffu, mx0, 1));
        mx0 = fmaxf(mx0, __shfl_xor_sync(0xffffffffu, mx0, 2));
        mx1 = fmaxf(mx1, __shfl_xor_sync(0xffffffffu, mx1, 1));
        mx1 = fmaxf(mx1, __shfl_xor_sync(0xffffffffu, mx1, 2));
        float mn0 = fmaxf(m0r, mx0), mn1 = fmaxf(m1r, mx1);
        float c0 = __expf(m0r - mn0), c1 = __expf(m1r - mn1);
        float s0 = 0.f, s1 = 0.f;
        #pragma unroll
        for (int nt = 0; nt < 16; nt++) {
            S[nt][0] = __expf(S[nt][0] - mn0); s0 += S[nt][0];
            S[nt][1] = __expf(S[nt][1] - mn0); s0 += S[nt][1];
            S[nt][2] = __expf(S[nt][2] - mn1); s1 += S[nt][2];
            S[nt][3] = __expf(S[nt][3] - mn1); s1 += S[nt][3];
        }
        s0 += __shfl_xor_sync(0xffffffffu, s0, 1);
        s0 += __shfl_xor_sync(0xffffffffu, s0, 2);
        s1 += __shfl_xor_sync(0xffffffffu, s1, 1);
        s1 += __shfl_xor_sync(0xffffffffu, s1, 2);
        l0r = l0r * c0 + s0; m0r = mn0;
        l1r = l1r * c1 + s1; m1r = mn1;
        #pragma unroll
        for (int nt = 0; nt < 8; nt++) {
            O[nt][0] *= c0; O[nt][1] *= c0;
            O[nt][2] *= c1; O[nt][3] *= c1;
        }

        // O += P V  (P fragments built register-only from S)
        #pragma unroll
        for (int ks2 = 0; ks2 < 8; ks2++) {
            uint32_t pa0 = pack2(S[2*ks2][0],   S[2*ks2][1]);
            uint32_t pa1 = pack2(S[2*ks2][2],   S[2*ks2][3]);
            uint32_t pa2 = pack2(S[2*ks2+1][0], S[2*ks2+1][1]);
            uint32_t pa3 = pack2(S[2*ks2+1][2], S[2*ks2+1][3]);
            #pragma unroll
            for (int p2 = 0; p2 < 4; p2++) {
                uint32_t b0, b1, b2, b3;
                uint32_t vd = sV + (uint32_t)((p2 * 16 + (g >> 1) * 8 + r) * 272
                                              + ks2 * 32 + (g & 1) * 16);
                LDSM_X4(b0, b1, b2, b3, vd);
                MMA4(O[2*p2],   pa0, pa1, pa2, pa3, b0, b1);
                MMA4(O[2*p2+1], pa0, pa1, pa2, pa3, b2, b3);
            }
        }
    }

    // Epilogue: att layout [b][c=h*64+d][n=i]
    float* ap = att + ((size_t)b * CC + hh * CHD) * NTOK;
    float inv0 = 1.f / l0r, inv1 = 1.f / l1r;
    int ig0 = q0 + w * 16 + qrow, ig1 = ig0 + 8;
    #pragma unroll
    for (int nt = 0; nt < 8; nt++) {
        int d0 = nt * 8 + qcol;
        ap[(size_t)(d0 + 0) * NTOK + ig0] = O[nt][0] * inv0;
        ap[(size_t)(d0 + 1) * NTOK + ig0] = O[nt][1] * inv0;
        ap[(size_t)(d0 + 0) * NTOK + ig1] = O[nt][2] * inv1;
        ap[(size_t)(d0 + 1) * NTOK + ig1] = O[nt][3] * inv1;
    }
}

// ---------------------------------------------------------------------------
extern "C" void kernel_launch(void* const* d_in, const int* in_sizes, int n_in,
                              void* d_out, int out_size) {
    (void)in_sizes; (void)n_in; (void)out_size;
    const float* x  = (const float*)d_in[0];
    const float* nw = (const float*)d_in[1];
    const float* nb = (const float*)d_in[2];
    const float* qw = (const float*)d_in[3];
    const float* qb = (const float*)d_in[4];
    const float* pw = (const float*)d_in[5];
    const float* pb = (const float*)d_in[6];
    float* out = (float*)d_out;

    float *xn, *qkv, *att;
    cudaGetSymbolAddress((void**)&xn,  g_xn);
    cudaGetSymbolAddress((void**)&qkv, g_qkv);
    cudaGetSymbolAddress((void**)&att, g_att);
    cudaFuncSetAttribute(gemm_hmma<false>, cudaFuncAttributeMaxDynamicSharedMemorySize, GEMM_SMEM);
    cudaFuncSetAttribute(gemm_hmma<true>,  cudaFuncAttributeMaxDynamicSharedMemorySize, GEMM_SMEM);
    cudaFuncSetAttribute(flash_hmma, cudaFuncAttributeMaxDynamicSharedMemorySize, FLASH_SMEM);

    gn_kernel<<<BB * NG, 256>>>(x, nw, nb, xn);
    gemm_hmma<false><<<dim3(8, 12, BB), 256, GEMM_SMEM>>>(qw, xn, qb, nullptr, qkv, 1536);
    flash_hmma<<<dim3(8, HEADS, BB), 256, FLASH_SMEM>>>(qkv, att);
    gemm_hmma<true><<<dim3(8, 4, BB), 256, GEMM_SMEM>>>(pw, att, pb, x, out, 512);
}

// round 5
// speedup vs baseline: 4.6988x; 1.5091x over previous
#include <cuda_runtime.h>
#include <cuda_fp16.h>
#include <cstdint>

#define BB   16
#define CC   512
#define NTOK 1024
#define HEADS 8
#define CHD  64
#define NG   32
#define CPG  16
#define EPSV 1e-5f

// Scratch (static device arrays: allocation-free per harness rules), all fp16
__device__ __half g_wq[1536 * 512];                 // qkv weights fp16
__device__ __half g_wp[512 * 512];                  // proj weights fp16
__device__ __half g_xh[BB * NTOK * CC];             // x_norm hi, [b][n][c]
__device__ __half g_xl[BB * NTOK * CC];             // x_norm lo
__device__ __half g_qt[BB * NTOK * CC];             // Q (scaled), [b][n][c]
__device__ __half g_kt[BB * NTOK * CC];             // K, [b][n][c]
__device__ __half g_v [BB * CC * NTOK];             // V, [b][c][n]
__device__ __half g_ah[BB * NTOK * CC];             // att hi, [b][n][c]
__device__ __half g_al[BB * NTOK * CC];             // att lo

// ===========================================================================
// Helpers
// ===========================================================================
#define SWZ(x) ((uint32_t)(x) ^ ((((uint32_t)(x)) >> 3) & 0x70u))

static __device__ __forceinline__ uint32_t smem_u32(const void* p) {
    uint32_t a;
    asm("{ .reg .u64 t; cvta.to.shared.u64 t, %1; cvt.u32.u64 %0, t; }" : "=r"(a) : "l"(p));
    return a;
}

#define CPA16(dst, src) \
    asm volatile("cp.async.cg.shared.global [%0], [%1], 16;" :: "r"(dst), "l"(src))
#define CP_COMMIT() asm volatile("cp.async.commit_group;")
#define CP_WAIT1()  asm volatile("cp.async.wait_group 1;")
#define CP_WAIT0()  asm volatile("cp.async.wait_group 0;")

#define LDSM_X4(r0, r1, r2, r3, addr) \
    asm volatile("ldmatrix.sync.aligned.m8n8.x4.shared.b16 {%0,%1,%2,%3}, [%4];" \
        : "=r"(r0), "=r"(r1), "=r"(r2), "=r"(r3) : "r"(addr))

#define MMA4(c, a0, a1, a2, a3, b0, b1) \
    asm volatile("mma.sync.aligned.m16n8k16.row.col.f32.f16.f16.f32 " \
        "{%0,%1,%2,%3}, {%4,%5,%6,%7}, {%8,%9}, {%0,%1,%2,%3};" \
        : "+f"((c)[0]), "+f"((c)[1]), "+f"((c)[2]), "+f"((c)[3]) \
        : "r"(a0), "r"(a1), "r"(a2), "r"(a3), "r"(b0), "r"(b1))

static __device__ __forceinline__ uint32_t pack2(float a, float b) {
    __half2 h = __floats2half2_rn(a, b);
    return *reinterpret_cast<uint32_t*>(&h);
}

// ---------------------------------------------------------------------------
// Kernel 0: convert weights fp32 -> fp16 (runs once per launch, tiny)
// ---------------------------------------------------------------------------
__global__ void prep_w(const float* __restrict__ qw, const float* __restrict__ pw) {
    int idx = blockIdx.x * 256 + threadIdx.x;      // float4 index
    const int NQ = 1536 * 512 / 4;                 // 196608
    const int NP = 512 * 512 / 4;                  // 65536
    if (idx < NQ) {
        float4 v = ((const float4*)qw)[idx];
        *(uint2*)&g_wq[idx * 4] = make_uint2(pack2(v.x, v.y), pack2(v.z, v.w));
    } else if (idx < NQ + NP) {
        int j = idx - NQ;
        float4 v = ((const float4*)pw)[j];
        *(uint2*)&g_wp[j * 4] = make_uint2(pack2(v.x, v.y), pack2(v.z, v.w));
    }
}

// ---------------------------------------------------------------------------
// Kernel 1: GroupNorm -> fp16 hi/lo, transposed to [b][n][c].
// Block = (batch, group): 16 channels x 1024 tokens. smem tile transpose.
// ---------------------------------------------------------------------------
__global__ void gn_kernel(const float* __restrict__ x, const float* __restrict__ w,
                          const float* __restrict__ bias) {
    __shared__ __half smh[64 * 24], sml[64 * 24];   // [n][c] pad 24
    int bg = blockIdx.x;
    int b = bg / NG, g = bg % NG;
    const float* xg = x + ((size_t)b * CC + g * CPG) * NTOK;
    const float4* xp = (const float4*)xg;

    float s = 0.f, ss = 0.f;
    for (int i = threadIdx.x; i < CPG * NTOK / 4; i += 256) {
        float4 v = xp[i];
        s  += v.x + v.y + v.z + v.w;
        ss += v.x * v.x + v.y * v.y + v.z * v.z + v.w * v.w;
    }
    #pragma unroll
    for (int off = 16; off; off >>= 1) {
        s  += __shfl_xor_sync(0xffffffffu, s, off);
        ss += __shfl_xor_sync(0xffffffffu, ss, off);
    }
    __shared__ float rs[8], rss[8];
    __shared__ float bmean, binv;
    int wid = threadIdx.x >> 5, lid = threadIdx.x & 31;
    if (lid == 0) { rs[wid] = s; rss[wid] = ss; }
    __syncthreads();
    if (threadIdx.x == 0) {
        float S = 0.f, SS = 0.f;
        #pragma unroll
        for (int i = 0; i < 8; i++) { S += rs[i]; SS += rss[i]; }
        float mean = S * (1.0f / (CPG * NTOK));
        float var  = SS * (1.0f / (CPG * NTOK)) - mean * mean;
        bmean = mean;
        binv  = rsqrtf(var + EPSV);
    }
    __syncthreads();
    float mean = bmean, inv = binv;

    int c  = threadIdx.x >> 4;          // 0..15
    int n4 = (threadIdx.x & 15) * 4;    // 0..60
    float wc = w[g * CPG + c] * inv;
    float bc = bias[g * CPG + c] - mean * wc;

    for (int nt = 0; nt < 16; nt++) {
        int n0 = nt * 64;
        float4 v = *(const float4*)&xg[(size_t)c * NTOK + n0 + n4];
        float vv[4] = {v.x * wc + bc, v.y * wc + bc, v.z * wc + bc, v.w * wc + bc};
        #pragma unroll
        for (int j = 0; j < 4; j++) {
            __half h = __float2half_rn(vv[j]);
            smh[(n4 + j) * 24 + c] = h;
            sml[(n4 + j) * 24 + c] = __float2half_rn(vv[j] - __half2float(h));
        }
        __syncthreads();
        int t = threadIdx.x;
        int n = (t & 127) >> 1, ch = t & 1;
        uint4 val = (t < 128) ? *(uint4*)&smh[n * 24 + ch * 8]
                              : *(uint4*)&sml[n * 24 + ch * 8];
        __half* dst = (t < 128) ? g_xh : g_xl;
        *(uint4*)&dst[((size_t)b * NTOK + n0 + n) * CC + g * CPG + ch * 8] = val;
        __syncthreads();
    }
}

// ---------------------------------------------------------------------------
// Kernel 2/4: fp16 HMMA GEMM, cp.async double-buffered, 2-term split on B.
// Y[b,m,n] = sum_k W[m,k] * X[b,n,k] (X token-major hi/lo halves)
// CTA 128m x 128n x K512 (8 K-blocks of 64). Stage = A 16K + Bh 16K + Bl 16K.
// MODE 0: proj -> fp32 out + bias + residual
// MODE 1: qkv  -> q/k transposed fp16 [n][c] (q scaled 1/8), v native fp16
// ---------------------------------------------------------------------------
#define GT_SMEM (2 * 49152)

template <int MODE>
__global__ void __launch_bounds__(256, 2)
gemm16(const __half* __restrict__ Wm, const __half* __restrict__ Bhp,
       const __half* __restrict__ Blp, const float* __restrict__ bias,
       const float* __restrict__ Rz, float* __restrict__ Yf, int Mtot) {
    extern __shared__ char smem[];
    const uint32_t sb = smem_u32(smem);
    const int tid = threadIdx.x, lane = tid & 31, w = tid >> 5;
    const int wm = w & 1, wn = w >> 1;
    const int g = lane >> 3, r = lane & 7;
    const int qrow = lane >> 2, qcol = (lane & 3) * 2;
    const int n0 = blockIdx.x * 128, m0 = blockIdx.y * 128, b = blockIdx.z;
    const __half* Bh = Bhp + (size_t)b * NTOK * CC;
    const __half* Bl = Blp + (size_t)b * NTOK * CC;

    float acc[4][4][4];
    #pragma unroll
    for (int i = 0; i < 4; i++)
        #pragma unroll
        for (int j = 0; j < 4; j++)
            #pragma unroll
            for (int e = 0; e < 4; e++) acc[i][j][e] = 0.f;

    // ---- stage fill: 12 x 16B cp.async per thread ----
    auto fill = [&](int kb, int st) {
        const uint32_t base = sb + (uint32_t)st * 49152u;
        #pragma unroll
        for (int q = 0; q < 4; q++) {
            int id = q * 256 + tid;
            int row = id >> 3, ch = id & 7;
            uint32_t so = SWZ(row * 128 + ch * 16);
            CPA16(base + so, Wm + (size_t)(m0 + row) * CC + kb * 64 + ch * 8);
            CPA16(base + 16384u + so, Bh + (size_t)(n0 + row) * CC + kb * 64 + ch * 8);
            CPA16(base + 32768u + so, Bl + (size_t)(n0 + row) * CC + kb * 64 + ch * 8);
        }
    };

    fill(0, 0); CP_COMMIT();
    fill(1, 1); CP_COMMIT();

    for (int kb = 0; kb < 8; kb++) {
        if (kb == 7) { CP_WAIT0(); } else { CP_WAIT1(); }
        __syncthreads();
        const uint32_t sA  = sb + (uint32_t)(kb & 1) * 49152u;
        const uint32_t sBh = sA + 16384u, sBl = sA + 32768u;

        #pragma unroll
        for (int ks = 0; ks < 4; ks++) {
            uint32_t a[4][4];
            #pragma unroll
            for (int mt = 0; mt < 4; mt++) {
                uint32_t ad = sA + SWZ((wm * 64 + mt * 16 + (g & 1) * 8 + r) * 128
                                       + ks * 32 + (g >> 1) * 16);
                LDSM_X4(a[mt][0], a[mt][1], a[mt][2], a[mt][3], ad);
            }
            uint32_t bb[4][2];
            #pragma unroll
            for (int p = 0; p < 2; p++) {
                uint32_t bd = sBh + SWZ((wn * 32 + p * 16 + (g >> 1) * 8 + r) * 128
                                        + ks * 32 + (g & 1) * 16);
                LDSM_X4(bb[2*p][0], bb[2*p][1], bb[2*p+1][0], bb[2*p+1][1], bd);
            }
            #pragma unroll
            for (int mt = 0; mt < 4; mt++)
                #pragma unroll
                for (int nt = 0; nt < 4; nt++)
                    MMA4(acc[mt][nt], a[mt][0], a[mt][1], a[mt][2], a[mt][3],
                         bb[nt][0], bb[nt][1]);
            #pragma unroll
            for (int p = 0; p < 2; p++) {
                uint32_t bd = sBl + SWZ((wn * 32 + p * 16 + (g >> 1) * 8 + r) * 128
                                        + ks * 32 + (g & 1) * 16);
                LDSM_X4(bb[2*p][0], bb[2*p][1], bb[2*p+1][0], bb[2*p+1][1], bd);
            }
            #pragma unroll
            for (int mt = 0; mt < 4; mt++)
                #pragma unroll
                for (int nt = 0; nt < 4; nt++)
                    MMA4(acc[mt][nt], a[mt][0], a[mt][1], a[mt][2], a[mt][3],
                         bb[nt][0], bb[nt][1]);
        }
        __syncthreads();
        if (kb + 2 < 8) { fill(kb + 2, kb & 1); CP_COMMIT(); }
    }

    if (MODE == 0) {
        // proj: fp32 out + bias + residual, native [m][n]
        #pragma unroll
        for (int mt = 0; mt < 4; mt++) {
            int mr0 = m0 + wm * 64 + mt * 16 + qrow;
            float bv0 = bias[mr0], bv1 = bias[mr0 + 8];
            #pragma unroll
            for (int nt = 0; nt < 4; nt++) {
                int col = n0 + wn * 32 + nt * 8 + qcol;
                size_t o0 = ((size_t)b * Mtot + mr0) * NTOK + col;
                size_t o1 = o0 + (size_t)8 * NTOK;
                float2 z0 = *(const float2*)&Rz[o0];
                float2 z1 = *(const float2*)&Rz[o1];
                *(float2*)&Yf[o0] = make_float2(acc[mt][nt][0] + bv0 + z0.x,
                                                acc[mt][nt][1] + bv0 + z0.y);
                *(float2*)&Yf[o1] = make_float2(acc[mt][nt][2] + bv1 + z1.x,
                                                acc[mt][nt][3] + bv1 + z1.y);
            }
        }
    } else {
        if (m0 < 1024) {
            // q/k: smem-staged transpose -> [n][c] fp16 (q scaled 1/8)
            const float scale = (m0 < 512) ? 0.125f : 1.0f;
            __half* dst = (m0 < 512) ? g_qt : g_kt;
            const int sec = (m0 < 512) ? m0 : m0 - 512;
            __half* smT = (__half*)smem;  // [128n][136m]
            __syncthreads();
            #pragma unroll
            for (int mt = 0; mt < 4; mt++) {
                int mr = wm * 64 + mt * 16 + qrow;
                float bv0 = bias[m0 + mr], bv1 = bias[m0 + mr + 8];
                #pragma unroll
                for (int nt = 0; nt < 4; nt++) {
                    int col = wn * 32 + nt * 8 + qcol;
                    smT[(col    ) * 136 + mr    ] = __float2half_rn((acc[mt][nt][0] + bv0) * scale);
                    smT[(col + 1) * 136 + mr    ] = __float2half_rn((acc[mt][nt][1] + bv0) * scale);
                    smT[(col    ) * 136 + mr + 8] = __float2half_rn((acc[mt][nt][2] + bv1) * scale);
                    smT[(col + 1) * 136 + mr + 8] = __float2half_rn((acc[mt][nt][3] + bv1) * scale);
                }
            }
            __syncthreads();
            int n = tid >> 1;
            #pragma unroll
            for (int cc = 0; cc < 8; cc++) {
                int mch = (tid & 1) * 8 + cc;
                uint4 v = *(uint4*)&smT[n * 136 + mch * 8];
                *(uint4*)&dst[((size_t)b * NTOK + n0 + n) * CC + sec + mch * 8] = v;
            }
        } else {
            // v: native [c][n] fp16
            #pragma unroll
            for (int mt = 0; mt < 4; mt++) {
                int mr = m0 - 1024 + wm * 64 + mt * 16 + qrow;
                float bv0 = bias[m0 + wm * 64 + mt * 16 + qrow];
                float bv1 = bias[m0 + wm * 64 + mt * 16 + qrow + 8];
                #pragma unroll
                for (int nt = 0; nt < 4; nt++) {
                    int col = n0 + wn * 32 + nt * 8 + qcol;
                    size_t o0 = ((size_t)b * CC + mr) * NTOK + col;
                    size_t o1 = o0 + (size_t)8 * NTOK;
                    *(uint32_t*)&g_v[o0] = pack2(acc[mt][nt][0] + bv0, acc[mt][nt][1] + bv0);
                    *(uint32_t*)&g_v[o1] = pack2(acc[mt][nt][2] + bv1, acc[mt][nt][3] + bv1);
                }
            }
        }
    }
}

// ---------------------------------------------------------------------------
// Kernel 3: fp16 HMMA flash attention, cp.async double-buffered K/V.
// smem: Q[i][d] 16KB @0; 2 stages of (K[j][d] 16KB + V[d][j] 272B-pad 17KB).
// Q pre-scaled by 1/8. Output att hi/lo fp16 [b][n][c].
// ---------------------------------------------------------------------------
#define FLASH_SMEM (16384 + 2 * 33792)

__global__ void __launch_bounds__(256, 2)
flash16(const __half* __restrict__ Qt, const __half* __restrict__ Kt,
        const __half* __restrict__ Vg) {
    extern __shared__ char fsm[];
    const uint32_t sb = smem_u32(fsm);
    const int tid = threadIdx.x, lane = tid & 31, w = tid >> 5;
    const int g = lane >> 3, r = lane & 7;
    const int qrow = lane >> 2, qcol = (lane & 3) * 2;
    const int qb = blockIdx.x, hh = blockIdx.y, b = blockIdx.z;
    const int q0 = qb * 128;

    auto fillKV = [&](int kt, int st) {
        const uint32_t base = sb + 16384u + (uint32_t)st * 33792u;
        const int k0 = kt * 128;
        #pragma unroll
        for (int q = 0; q < 4; q++) {
            int id = q * 256 + tid;
            int j = id >> 3, ch = id & 7;
            CPA16(base + SWZ(j * 128 + ch * 16),
                  Kt + ((size_t)b * NTOK + k0 + j) * CC + hh * CHD + ch * 8);
            int d = id >> 4, ch2 = id & 15;
            CPA16(base + 16384u + d * 272 + ch2 * 16,
                  Vg + ((size_t)b * CC + hh * CHD + d) * NTOK + k0 + ch2 * 8);
        }
    };

    // Q fill + stage 0 in group 0
    #pragma unroll
    for (int q = 0; q < 4; q++) {
        int id = q * 256 + tid;
        int i = id >> 3, ch = id & 7;
        CPA16(sb + SWZ(i * 128 + ch * 16),
              Qt + ((size_t)b * NTOK + q0 + i) * CC + hh * CHD + ch * 8);
    }
    fillKV(0, 0); CP_COMMIT();
    fillKV(1, 1); CP_COMMIT();

    float m0r = -1e30f, m1r = -1e30f, l0r = 0.f, l1r = 0.f;
    float O[8][4];
    #pragma unroll
    for (int i = 0; i < 8; i++)
        #pragma unroll
        for (int e = 0; e < 4; e++) O[i][e] = 0.f;

    for (int kt = 0; kt < 8; kt++) {
        if (kt == 7) { CP_WAIT0(); } else { CP_WAIT1(); }
        __syncthreads();
        const uint32_t sK = sb + 16384u + (uint32_t)(kt & 1) * 33792u;
        const uint32_t sV = sK + 16384u;

        float S[16][4];
        #pragma unroll
        for (int nt = 0; nt < 16; nt++)
            #pragma unroll
            for (int e = 0; e < 4; e++) S[nt][e] = 0.f;

        #pragma unroll
        for (int ks = 0; ks < 4; ks++) {
            uint32_t a0, a1, a2, a3;
            uint32_t ad = sb + SWZ((w * 16 + (g & 1) * 8 + r) * 128
                                   + ks * 32 + (g >> 1) * 16);
            LDSM_X4(a0, a1, a2, a3, ad);
            #pragma unroll
            for (int p = 0; p < 8; p++) {
                uint32_t b0, b1, b2, b3;
                uint32_t bd = sK + SWZ((p * 16 + (g >> 1) * 8 + r) * 128
                                       + ks * 32 + (g & 1) * 16);
                LDSM_X4(b0, b1, b2, b3, bd);
                MMA4(S[2*p],   a0, a1, a2, a3, b0, b1);
                MMA4(S[2*p+1], a0, a1, a2, a3, b2, b3);
            }
        }

        float mx0 = -1e30f, mx1 = -1e30f;
        #pragma unroll
        for (int nt = 0; nt < 16; nt++) {
            mx0 = fmaxf(mx0, fmaxf(S[nt][0], S[nt][1]));
            mx1 = fmaxf(mx1, fmaxf(S[nt][2], S[nt][3]));
        }
        mx0 = fmaxf(mx0, __shfl_xor_sync(0xffffffffu, mx0, 1));
        mx0 = fmaxf(mx0, __shfl_xor_sync(0xffffffffu, mx0, 2));
        mx1 = fmaxf(mx1, __shfl_xor_sync(0xffffffffu, mx1, 1));
        mx1 = fmaxf(mx1, __shfl_xor_sync(0xffffffffu, mx1, 2));
        float mn0 = fmaxf(m0r, mx0), mn1 = fmaxf(m1r, mx1);
        float c0 = __expf(m0r - mn0), c1 = __expf(m1r - mn1);
        float s0 = 0.f, s1 = 0.f;
        #pragma unroll
        for (int nt = 0; nt < 16; nt++) {
            S[nt][0] = __expf(S[nt][0] - mn0); s0 += S[nt][0];
            S[nt][1] = __expf(S[nt][1] - mn0); s0 += S[nt][1];
            S[nt][2] = __expf(S[nt][2] - mn1); s1 += S[nt][2];
            S[nt][3] = __expf(S[nt][3] - mn1); s1 += S[nt][3];
        }
        s0 += __shfl_xor_sync(0xffffffffu, s0, 1);
        s0 += __shfl_xor_sync(0xffffffffu, s0, 2);
        s1 += __shfl_xor_sync(0xffffffffu, s1, 1);
        s1 += __shfl_xor_sync(0xffffffffu, s1, 2);
        l0r = l0r * c0 + s0; m0r = mn0;
        l1r = l1r * c1 + s1; m1r = mn1;
        #pragma unroll
        for (int nt = 0; nt < 8; nt++) {
            O[nt][0] *= c0; O[nt][1] *= c0;
            O[nt][2] *= c1; O[nt][3] *= c1;
        }

        #pragma unroll
        for (int ks2 = 0; ks2 < 8; ks2++) {
            uint32_t pa0 = pack2(S[2*ks2][0],   S[2*ks2][1]);
            uint32_t pa1 = pack2(S[2*ks2][2],   S[2*ks2][3]);
            uint32_t pa2 = pack2(S[2*ks2+1][0], S[2*ks2+1][1]);
            uint32_t pa3 = pack2(S[2*ks2+1][2], S[2*ks2+1][3]);
            #pragma unroll
            for (int p2 = 0; p2 < 4; p2++) {
                uint32_t b0, b1, b2, b3;
                uint32_t vd = sV + (uint32_t)((p2 * 16 + (g >> 1) * 8 + r) * 272
                                              + ks2 * 32 + (g & 1) * 16);
                LDSM_X4(b0, b1, b2, b3, vd);
                MMA4(O[2*p2],   pa0, pa1, pa2, pa3, b0, b1);
                MMA4(O[2*p2+1], pa0, pa1, pa2, pa3, b2, b3);
            }
        }
        __syncthreads();
        if (kt + 2 < 8) { fillKV(kt + 2, kt & 1); CP_COMMIT(); }
    }

    // Epilogue: att hi/lo fp16, [b][n][c]
    float inv0 = 1.f / l0r, inv1 = 1.f / l1r;
    int ig0 = q0 + w * 16 + qrow, ig1 = ig0 + 8;
    size_t r0 = ((size_t)b * NTOK + ig0) * CC + hh * CHD + qcol;
    size_t r1 = ((size_t)b * NTOK + ig1) * CC + hh * CHD + qcol;
    #pragma unroll
    for (int nt = 0; nt < 8; nt++) {
        float v0 = O[nt][0] * inv0, v1 = O[nt][1] * inv0;
        float v2 = O[nt][2] * inv1, v3 = O[nt][3] * inv1;
        __half h0 = __float2half_rn(v0), h1 = __float2half_rn(v1);
        __half h2 = __float2half_rn(v2), h3 = __float2half_rn(v3);
        *(uint32_t*)&g_ah[r0 + nt * 8] =
            (uint32_t)__half_as_ushort(h0) | ((uint32_t)__half_as_ushort(h1) << 16);
        *(uint32_t*)&g_al[r0 + nt * 8] =
            pack2(v0 - __half2float(h0), v1 - __half2float(h1));
        *(uint32_t*)&g_ah[r1 + nt * 8] =
            (uint32_t)__half_as_ushort(h2) | ((uint32_t)__half_as_ushort(h3) << 16);
        *(uint32_t*)&g_al[r1 + nt * 8] =
            pack2(v2 - __half2float(h2), v3 - __half2float(h3));
    }
}

// ---------------------------------------------------------------------------
extern "C" void kernel_launch(void* const* d_in, const int* in_sizes, int n_in,
                              void* d_out, int out_size) {
    (void)in_sizes; (void)n_in; (void)out_size;
    const float* x  = (const float*)d_in[0];
    const float* nw = (const float*)d_in[1];
    const float* nb = (const float*)d_in[2];
    const float* qw = (const float*)d_in[3];
    const float* qb = (const float*)d_in[4];
    const float* pw = (const float*)d_in[5];
    const float* pb = (const float*)d_in[6];
    float* out = (float*)d_out;

    __half *wq, *wp, *xh, *xl, *qt, *kt, *vv, *ah, *al;
    cudaGetSymbolAddress((void**)&wq, g_wq);
    cudaGetSymbolAddress((void**)&wp, g_wp);
    cudaGetSymbolAddress((void**)&xh, g_xh);
    cudaGetSymbolAddress((void**)&xl, g_xl);
    cudaGetSymbolAddress((void**)&qt, g_qt);
    cudaGetSymbolAddress((void**)&kt, g_kt);
    cudaGetSymbolAddress((void**)&vv, g_v);
    cudaGetSymbolAddress((void**)&ah, g_ah);
    cudaGetSymbolAddress((void**)&al, g_al);
    (void)wq; (void)wp; (void)xh; (void)xl; (void)qt; (void)kt;
    (void)vv; (void)ah; (void)al;

    cudaFuncSetAttribute(gemm16<0>, cudaFuncAttributeMaxDynamicSharedMemorySize, GT_SMEM);
    cudaFuncSetAttribute(gemm16<1>, cudaFuncAttributeMaxDynamicSharedMemorySize, GT_SMEM);
    cudaFuncSetAttribute(flash16, cudaFuncAttributeMaxDynamicSharedMemorySize, FLASH_SMEM);

    prep_w<<<1024, 256>>>(qw, pw);
    gn_kernel<<<BB * NG, 256>>>(x, nw, nb);
    gemm16<1><<<dim3(8, 12, BB), 256, GT_SMEM>>>(wq, xh, xl, qb, nullptr, nullptr, 1536);
    flash16<<<dim3(8, HEADS, BB), 256, FLASH_SMEM>>>(qt, kt, vv);
    gemm16<0><<<dim3(8, 4, BB), 256, GT_SMEM>>>(wp, ah, al, pb, x, out, 512);
}

// round 6
// speedup vs baseline: 6.3270x; 1.3465x over previous
#include <cuda_runtime.h>
#include <cuda_fp16.h>
#include <cstdint>

#define BB   16
#define CC   512
#define NTOK 1024
#define HEADS 8
#define CHD  64
#define NG   32
#define CPG  16
#define EPSV 1e-5f
#define QSCALE 0.18033688f   // 0.125 * log2(e)

// Scratch (static device arrays), all fp16
__device__ __half g_wq[1536 * 512];                 // qkv weights fp16
__device__ __half g_wp[512 * 512];                  // proj weights fp16
__device__ __half g_xh[BB * NTOK * CC];             // x_norm, [b][n][c]
__device__ __half g_qt[BB * NTOK * CC];             // Q (scaled), [b][n][c]
__device__ __half g_kt[BB * NTOK * CC];             // K, [b][n][c]
__device__ __half g_v [BB * CC * NTOK];             // V, [b][c][n]
__device__ __half g_ah[BB * NTOK * CC];             // att, [b][n][c]

// ===========================================================================
// Helpers
// ===========================================================================
#define SWZ(x) ((uint32_t)(x) ^ ((((uint32_t)(x)) >> 3) & 0x70u))

static __device__ __forceinline__ uint32_t smem_u32(const void* p) {
    uint32_t a;
    asm("{ .reg .u64 t; cvta.to.shared.u64 t, %1; cvt.u32.u64 %0, t; }" : "=r"(a) : "l"(p));
    return a;
}

#define CPA16(dst, src) \
    asm volatile("cp.async.cg.shared.global [%0], [%1], 16;" :: "r"(dst), "l"(src))
#define CP_COMMIT() asm volatile("cp.async.commit_group;")
#define CP_WAIT1()  asm volatile("cp.async.wait_group 1;")
#define CP_WAIT0()  asm volatile("cp.async.wait_group 0;")

#define LDSM_X4(r0, r1, r2, r3, addr) \
    asm volatile("ldmatrix.sync.aligned.m8n8.x4.shared.b16 {%0,%1,%2,%3}, [%4];" \
        : "=r"(r0), "=r"(r1), "=r"(r2), "=r"(r3) : "r"(addr))

#define MMA4(c, a0, a1, a2, a3, b0, b1) \
    asm volatile("mma.sync.aligned.m16n8k16.row.col.f32.f16.f16.f32 " \
        "{%0,%1,%2,%3}, {%4,%5,%6,%7}, {%8,%9}, {%0,%1,%2,%3};" \
        : "+f"((c)[0]), "+f"((c)[1]), "+f"((c)[2]), "+f"((c)[3]) \
        : "r"(a0), "r"(a1), "r"(a2), "r"(a3), "r"(b0), "r"(b1))

static __device__ __forceinline__ uint32_t pack2(float a, float b) {
    __half2 h = __floats2half2_rn(a, b);
    return *reinterpret_cast<uint32_t*>(&h);
}

// ---------------------------------------------------------------------------
// Kernel 0: convert weights fp32 -> fp16
// ---------------------------------------------------------------------------
__global__ void prep_w(const float* __restrict__ qw, const float* __restrict__ pw) {
    int idx = blockIdx.x * 256 + threadIdx.x;
    const int NQ = 1536 * 512 / 4;
    const int NP = 512 * 512 / 4;
    if (idx < NQ) {
        float4 v = ((const float4*)qw)[idx];
        *(uint2*)&g_wq[idx * 4] = make_uint2(pack2(v.x, v.y), pack2(v.z, v.w));
    } else if (idx < NQ + NP) {
        int j = idx - NQ;
        float4 v = ((const float4*)pw)[j];
        *(uint2*)&g_wp[j * 4] = make_uint2(pack2(v.x, v.y), pack2(v.z, v.w));
    }
}

// ---------------------------------------------------------------------------
// Kernel 1: GroupNorm -> fp16, transposed to [b][n][c].
// ---------------------------------------------------------------------------
__global__ void gn_kernel(const float* __restrict__ x, const float* __restrict__ w,
                          const float* __restrict__ bias) {
    __shared__ __half smh[64 * 24];   // [n][c] pad 24
    int bg = blockIdx.x;
    int b = bg / NG, g = bg % NG;
    const float* xg = x + ((size_t)b * CC + g * CPG) * NTOK;
    const float4* xp = (const float4*)xg;

    float s = 0.f, ss = 0.f;
    for (int i = threadIdx.x; i < CPG * NTOK / 4; i += 256) {
        float4 v = xp[i];
        s  += v.x + v.y + v.z + v.w;
        ss += v.x * v.x + v.y * v.y + v.z * v.z + v.w * v.w;
    }
    #pragma unroll
    for (int off = 16; off; off >>= 1) {
        s  += __shfl_xor_sync(0xffffffffu, s, off);
        ss += __shfl_xor_sync(0xffffffffu, ss, off);
    }
    __shared__ float rs[8], rss[8];
    __shared__ float bmean, binv;
    int wid = threadIdx.x >> 5, lid = threadIdx.x & 31;
    if (lid == 0) { rs[wid] = s; rss[wid] = ss; }
    __syncthreads();
    if (threadIdx.x == 0) {
        float S = 0.f, SS = 0.f;
        #pragma unroll
        for (int i = 0; i < 8; i++) { S += rs[i]; SS += rss[i]; }
        float mean = S * (1.0f / (CPG * NTOK));
        float var  = SS * (1.0f / (CPG * NTOK)) - mean * mean;
        bmean = mean;
        binv  = rsqrtf(var + EPSV);
    }
    __syncthreads();
    float mean = bmean, inv = binv;

    int c  = threadIdx.x >> 4;
    int n4 = (threadIdx.x & 15) * 4;
    float wc = w[g * CPG + c] * inv;
    float bc = bias[g * CPG + c] - mean * wc;

    for (int nt = 0; nt < 16; nt++) {
        int n0 = nt * 64;
        float4 v = *(const float4*)&xg[(size_t)c * NTOK + n0 + n4];
        smh[(n4 + 0) * 24 + c] = __float2half_rn(v.x * wc + bc);
        smh[(n4 + 1) * 24 + c] = __float2half_rn(v.y * wc + bc);
        smh[(n4 + 2) * 24 + c] = __float2half_rn(v.z * wc + bc);
        smh[(n4 + 3) * 24 + c] = __float2half_rn(v.w * wc + bc);
        __syncthreads();
        int t = threadIdx.x;
        if (t < 128) {
            int n = t >> 1, ch = t & 1;
            uint4 val = *(uint4*)&smh[n * 24 + ch * 8];
            *(uint4*)&g_xh[((size_t)b * NTOK + n0 + n) * CC + g * CPG + ch * 8] = val;
        }
        __syncthreads();
    }
}

// ---------------------------------------------------------------------------
// Kernel 2/4: fp16 HMMA GEMM, cp.async double-buffered, single-term.
// Y[b,m,n] = sum_k W[m,k] * X[b,n,k]
// CTA 128m x 128n x K512 (8 K-blocks of 64). Stage = A 16K + B 16K.
// MODE 0: proj -> fp32 out + bias + residual
// MODE 1: qkv  -> q/k transposed fp16 [n][c] (q scaled), v native fp16
// ---------------------------------------------------------------------------
#define GT_SMEM 65536

template <int MODE>
__global__ void __launch_bounds__(256, 2)
gemm16(const __half* __restrict__ Wm, const __half* __restrict__ Bhp,
       const float* __restrict__ bias, const float* __restrict__ Rz,
       float* __restrict__ Yf, int Mtot) {
    extern __shared__ char smem[];
    const uint32_t sb = smem_u32(smem);
    const int tid = threadIdx.x, lane = tid & 31, w = tid >> 5;
    const int wm = w & 1, wn = w >> 1;
    const int g = lane >> 3, r = lane & 7;
    const int qrow = lane >> 2, qcol = (lane & 3) * 2;
    const int n0 = blockIdx.x * 128, m0 = blockIdx.y * 128, b = blockIdx.z;
    const __half* Bh = Bhp + (size_t)b * NTOK * CC;

    float acc[4][4][4];
    #pragma unroll
    for (int i = 0; i < 4; i++)
        #pragma unroll
        for (int j = 0; j < 4; j++)
            #pragma unroll
            for (int e = 0; e < 4; e++) acc[i][j][e] = 0.f;

    auto fill = [&](int kb, int st) {
        const uint32_t base = sb + (uint32_t)st * 32768u;
        #pragma unroll
        for (int q = 0; q < 4; q++) {
            int id = q * 256 + tid;
            int row = id >> 3, ch = id & 7;
            uint32_t so = SWZ(row * 128 + ch * 16);
            CPA16(base + so, Wm + (size_t)(m0 + row) * CC + kb * 64 + ch * 8);
            CPA16(base + 16384u + so, Bh + (size_t)(n0 + row) * CC + kb * 64 + ch * 8);
        }
    };

    fill(0, 0); CP_COMMIT();
    fill(1, 1); CP_COMMIT();

    for (int kb = 0; kb < 8; kb++) {
        if (kb == 7) { CP_WAIT0(); } else { CP_WAIT1(); }
        __syncthreads();
        const uint32_t sA = sb + (uint32_t)(kb & 1) * 32768u;
        const uint32_t sB = sA + 16384u;

        #pragma unroll
        for (int ks = 0; ks < 4; ks++) {
            uint32_t a[4][4];
            #pragma unroll
            for (int mt = 0; mt < 4; mt++) {
                uint32_t ad = sA + SWZ((wm * 64 + mt * 16 + (g & 1) * 8 + r) * 128
                                       + ks * 32 + (g >> 1) * 16);
                LDSM_X4(a[mt][0], a[mt][1], a[mt][2], a[mt][3], ad);
            }
            uint32_t bb[4][2];
            #pragma unroll
            for (int p = 0; p < 2; p++) {
                uint32_t bd = sB + SWZ((wn * 32 + p * 16 + (g >> 1) * 8 + r) * 128
                                       + ks * 32 + (g & 1) * 16);
                LDSM_X4(bb[2*p][0], bb[2*p][1], bb[2*p+1][0], bb[2*p+1][1], bd);
            }
            #pragma unroll
            for (int mt = 0; mt < 4; mt++)
                #pragma unroll
                for (int nt = 0; nt < 4; nt++)
                    MMA4(acc[mt][nt], a[mt][0], a[mt][1], a[mt][2], a[mt][3],
                         bb[nt][0], bb[nt][1]);
        }
        __syncthreads();
        if (kb + 2 < 8) { fill(kb + 2, kb & 1); CP_COMMIT(); }
    }

    if (MODE == 0) {
        #pragma unroll
        for (int mt = 0; mt < 4; mt++) {
            int mr0 = m0 + wm * 64 + mt * 16 + qrow;
            float bv0 = bias[mr0], bv1 = bias[mr0 + 8];
            #pragma unroll
            for (int nt = 0; nt < 4; nt++) {
                int col = n0 + wn * 32 + nt * 8 + qcol;
                size_t o0 = ((size_t)b * Mtot + mr0) * NTOK + col;
                size_t o1 = o0 + (size_t)8 * NTOK;
                float2 z0 = *(const float2*)&Rz[o0];
                float2 z1 = *(const float2*)&Rz[o1];
                *(float2*)&Yf[o0] = make_float2(acc[mt][nt][0] + bv0 + z0.x,
                                                acc[mt][nt][1] + bv0 + z0.y);
                *(float2*)&Yf[o1] = make_float2(acc[mt][nt][2] + bv1 + z1.x,
                                                acc[mt][nt][3] + bv1 + z1.y);
            }
        }
    } else {
        if (m0 < 1024) {
            // q/k: smem-staged transpose -> [n][c] fp16 (q scaled by QSCALE)
            const float scale = (m0 < 512) ? QSCALE : 1.0f;
            __half* dst = (m0 < 512) ? g_qt : g_kt;
            const int sec = (m0 < 512) ? m0 : m0 - 512;
            __half* smT = (__half*)smem;  // [128n][136m]
            __syncthreads();
            #pragma unroll
            for (int mt = 0; mt < 4; mt++) {
                int mr = wm * 64 + mt * 16 + qrow;
                float bv0 = bias[m0 + mr], bv1 = bias[m0 + mr + 8];
                #pragma unroll
                for (int nt = 0; nt < 4; nt++) {
                    int col = wn * 32 + nt * 8 + qcol;
                    smT[(col    ) * 136 + mr    ] = __float2half_rn((acc[mt][nt][0] + bv0) * scale);
                    smT[(col + 1) * 136 + mr    ] = __float2half_rn((acc[mt][nt][1] + bv0) * scale);
                    smT[(col    ) * 136 + mr + 8] = __float2half_rn((acc[mt][nt][2] + bv1) * scale);
                    smT[(col + 1) * 136 + mr + 8] = __float2half_rn((acc[mt][nt][3] + bv1) * scale);
                }
            }
            __syncthreads();
            int n = tid >> 1;
            #pragma unroll
            for (int cc = 0; cc < 8; cc++) {
                int mch = (tid & 1) * 8 + cc;
                uint4 v = *(uint4*)&smT[n * 136 + mch * 8];
                *(uint4*)&dst[((size_t)b * NTOK + n0 + n) * CC + sec + mch * 8] = v;
            }
        } else {
            // v: native [c][n] fp16
            #pragma unroll
            for (int mt = 0; mt < 4; mt++) {
                int mr = m0 - 1024 + wm * 64 + mt * 16 + qrow;
                float bv0 = bias[m0 + wm * 64 + mt * 16 + qrow];
                float bv1 = bias[m0 + wm * 64 + mt * 16 + qrow + 8];
                #pragma unroll
                for (int nt = 0; nt < 4; nt++) {
                    int col = n0 + wn * 32 + nt * 8 + qcol;
                    size_t o0 = ((size_t)b * CC + mr) * NTOK + col;
                    size_t o1 = o0 + (size_t)8 * NTOK;
                    *(uint32_t*)&g_v[o0] = pack2(acc[mt][nt][0] + bv0, acc[mt][nt][1] + bv0);
                    *(uint32_t*)&g_v[o1] = pack2(acc[mt][nt][2] + bv1, acc[mt][nt][3] + bv1);
                }
            }
        }
    }
}

// ---------------------------------------------------------------------------
// Kernel 3: fp16 HMMA flash attention, cp.async double-buffered K/V.
// Q pre-scaled by 0.125*log2e; softmax in log2 domain via exp2f.
// ---------------------------------------------------------------------------
#define FLASH_SMEM (16384 + 2 * 33792)

__global__ void __launch_bounds__(256, 2)
flash16(const __half* __restrict__ Qt, const __half* __restrict__ Kt,
        const __half* __restrict__ Vg) {
    extern __shared__ char fsm[];
    const uint32_t sb = smem_u32(fsm);
    const int tid = threadIdx.x, lane = tid & 31, w = tid >> 5;
    const int g = lane >> 3, r = lane & 7;
    const int qrow = lane >> 2, qcol = (lane & 3) * 2;
    const int qb = blockIdx.x, hh = blockIdx.y, b = blockIdx.z;
    const int q0 = qb * 128;

    auto fillKV = [&](int kt, int st) {
        const uint32_t base = sb + 16384u + (uint32_t)st * 33792u;
        const int k0 = kt * 128;
        #pragma unroll
        for (int q = 0; q < 4; q++) {
            int id = q * 256 + tid;
            int j = id >> 3, ch = id & 7;
            CPA16(base + SWZ(j * 128 + ch * 16),
                  Kt + ((size_t)b * NTOK + k0 + j) * CC + hh * CHD + ch * 8);
            int d = id >> 4, ch2 = id & 15;
            CPA16(base + 16384u + d * 272 + ch2 * 16,
                  Vg + ((size_t)b * CC + hh * CHD + d) * NTOK + k0 + ch2 * 8);
        }
    };

    #pragma unroll
    for (int q = 0; q < 4; q++) {
        int id = q * 256 + tid;
        int i = id >> 3, ch = id & 7;
        CPA16(sb + SWZ(i * 128 + ch * 16),
              Qt + ((size_t)b * NTOK + q0 + i) * CC + hh * CHD + ch * 8);
    }
    fillKV(0, 0); CP_COMMIT();
    fillKV(1, 1); CP_COMMIT();

    float m0r = -1e30f, m1r = -1e30f, l0r = 0.f, l1r = 0.f;
    float O[8][4];
    #pragma unroll
    for (int i = 0; i < 8; i++)
        #pragma unroll
        for (int e = 0; e < 4; e++) O[i][e] = 0.f;

    for (int kt = 0; kt < 8; kt++) {
        if (kt == 7) { CP_WAIT0(); } else { CP_WAIT1(); }
        __syncthreads();
        const uint32_t sK = sb + 16384u + (uint32_t)(kt & 1) * 33792u;
        const uint32_t sV = sK + 16384u;

        float S[16][4];
        #pragma unroll
        for (int nt = 0; nt < 16; nt++)
            #pragma unroll
            for (int e = 0; e < 4; e++) S[nt][e] = 0.f;

        #pragma unroll
        for (int ks = 0; ks < 4; ks++) {
            uint32_t a0, a1, a2, a3;
            uint32_t ad = sb + SWZ((w * 16 + (g & 1) * 8 + r) * 128
                                   + ks * 32 + (g >> 1) * 16);
            LDSM_X4(a0, a1, a2, a3, ad);
            #pragma unroll
            for (int p = 0; p < 8; p++) {
                uint32_t b0, b1, b2, b3;
                uint32_t bd = sK + SWZ((p * 16 + (g >> 1) * 8 + r) * 128
                                       + ks * 32 + (g & 1) * 16);
                LDSM_X4(b0, b1, b2, b3, bd);
                MMA4(S[2*p],   a0, a1, a2, a3, b0, b1);
                MMA4(S[2*p+1], a0, a1, a2, a3, b2, b3);
            }
        }

        float mx0 = -1e30f, mx1 = -1e30f;
        #pragma unroll
        for (int nt = 0; nt < 16; nt++) {
            mx0 = fmaxf(mx0, fmaxf(S[nt][0], S[nt][1]));
            mx1 = fmaxf(mx1, fmaxf(S[nt][2], S[nt][3]));
        }
        mx0 = fmaxf(mx0, __shfl_xor_sync(0xffffffffu, mx0, 1));
        mx0 = fmaxf(mx0, __shfl_xor_sync(0xffffffffu, mx0, 2));
        mx1 = fmaxf(mx1, __shfl_xor_sync(0xffffffffu, mx1, 1));
        mx1 = fmaxf(mx1, __shfl_xor_sync(0xffffffffu, mx1, 2));
        float mn0 = fmaxf(m0r, mx0), mn1 = fmaxf(m1r, mx1);
        float c0 = exp2f(m0r - mn0), c1 = exp2f(m1r - mn1);
        float s0 = 0.f, s1 = 0.f;
        #pragma unroll
        for (int nt = 0; nt < 16; nt++) {
            S[nt][0] = exp2f(S[nt][0] - mn0); s0 += S[nt][0];
            S[nt][1] = exp2f(S[nt][1] - mn0); s0 += S[nt][1];
            S[nt][2] = exp2f(S[nt][2] - mn1); s1 += S[nt][2];
            S[nt][3] = exp2f(S[nt][3] - mn1); s1 += S[nt][3];
        }
        s0 += __shfl_xor_sync(0xffffffffu, s0, 1);
        s0 += __shfl_xor_sync(0xffffffffu, s0, 2);
        s1 += __shfl_xor_sync(0xffffffffu, s1, 1);
        s1 += __shfl_xor_sync(0xffffffffu, s1, 2);
        l0r = l0r * c0 + s0; m0r = mn0;
        l1r = l1r * c1 + s1; m1r = mn1;
        #pragma unroll
        for (int nt = 0; nt < 8; nt++) {
            O[nt][0] *= c0; O[nt][1] *= c0;
            O[nt][2] *= c1; O[nt][3] *= c1;
        }

        #pragma unroll
        for (int ks2 = 0; ks2 < 8; ks2++) {
            uint32_t pa0 = pack2(S[2*ks2][0],   S[2*ks2][1]);
            uint32_t pa1 = pack2(S[2*ks2][2],   S[2*ks2][3]);
            uint32_t pa2 = pack2(S[2*ks2+1][0], S[2*ks2+1][1]);
            uint32_t pa3 = pack2(S[2*ks2+1][2], S[2*ks2+1][3]);
            #pragma unroll
            for (int p2 = 0; p2 < 4; p2++) {
                uint32_t b0, b1, b2, b3;
                uint32_t vd = sV + (uint32_t)((p2 * 16 + (g >> 1) * 8 + r) * 272
                                              + ks2 * 32 + (g & 1) * 16);
                LDSM_X4(b0, b1, b2, b3, vd);
                MMA4(O[2*p2],   pa0, pa1, pa2, pa3, b0, b1);
                MMA4(O[2*p2+1], pa0, pa1, pa2, pa3, b2, b3);
            }
        }
        __syncthreads();
        if (kt + 2 < 8) { fillKV(kt + 2, kt & 1); CP_COMMIT(); }
    }

    float inv0 = 1.f / l0r, inv1 = 1.f / l1r;
    int ig0 = q0 + w * 16 + qrow, ig1 = ig0 + 8;
    size_t r0 = ((size_t)b * NTOK + ig0) * CC + hh * CHD + qcol;
    size_t r1 = ((size_t)b * NTOK + ig1) * CC + hh * CHD + qcol;
    #pragma unroll
    for (int nt = 0; nt < 8; nt++) {
        *(uint32_t*)&g_ah[r0 + nt * 8] = pack2(O[nt][0] * inv0, O[nt][1] * inv0);
        *(uint32_t*)&g_ah[r1 + nt * 8] = pack2(O[nt][2] * inv1, O[nt][3] * inv1);
    }
}

// ---------------------------------------------------------------------------
extern "C" void kernel_launch(void* const* d_in, const int* in_sizes, int n_in,
                              void* d_out, int out_size) {
    (void)in_sizes; (void)n_in; (void)out_size;
    const float* x  = (const float*)d_in[0];
    const float* nw = (const float*)d_in[1];
    const float* nb = (const float*)d_in[2];
    const float* qw = (const float*)d_in[3];
    const float* qb = (const float*)d_in[4];
    const float* pw = (const float*)d_in[5];
    const float* pb = (const float*)d_in[6];
    float* out = (float*)d_out;

    __half *wq, *wp, *xh, *qt, *kt, *vv, *ah;
    cudaGetSymbolAddress((void**)&wq, g_wq);
    cudaGetSymbolAddress((void**)&wp, g_wp);
    cudaGetSymbolAddress((void**)&xh, g_xh);
    cudaGetSymbolAddress((void**)&qt, g_qt);
    cudaGetSymbolAddress((void**)&kt, g_kt);
    cudaGetSymbolAddress((void**)&vv, g_v);
    cudaGetSymbolAddress((void**)&ah, g_ah);

    cudaFuncSetAttribute(gemm16<0>, cudaFuncAttributeMaxDynamicSharedMemorySize, GT_SMEM);
    cudaFuncSetAttribute(gemm16<1>, cudaFuncAttributeMaxDynamicSharedMemorySize, GT_SMEM);
    cudaFuncSetAttribute(flash16, cudaFuncAttributeMaxDynamicSharedMemorySize, FLASH_SMEM);

    prep_w<<<1024, 256>>>(qw, pw);
    gn_kernel<<<BB * NG, 256>>>(x, nw, nb);
    gemm16<1><<<dim3(8, 12, BB), 256, GT_SMEM>>>(wq, xh, qb, nullptr, nullptr, 1536);
    flash16<<<dim3(8, HEADS, BB), 256, FLASH_SMEM>>>(qt, kt, vv);
    gemm16<0><<<dim3(8, 4, BB), 256, GT_SMEM>>>(wp, ah, pb, x, out, 512);
}